// round 10
// baseline (speedup 1.0000x reference)
#include <cuda_runtime.h>

#define DD 128
#define MAXN 50176

// Scratch (device globals: allocation inside kernel_launch is forbidden)
__device__ float g_deg[MAXN];
__device__ float g_dinv[MAXN];
__device__ __align__(16) float g_s[(size_t)MAXN * DD];   // ~25.7 MB, fits L2
__device__ float g_pool[DD];
__device__ int   g_is64;     // edge_index dtype flag (auto-detected on device)

// ---------------------------------------------------------------- dtype sniff
// int64 little-endian with values < 2^31  =>  all odd 32-bit words are 0.
// 256 random int32 indices in [0,50000) being zero at odd positions: impossible.
__global__ void k_sniff(const int* __restrict__ ei, int E) {
    int nz = 0;
    int limit = 2 * E < 512 ? 2 * E : 512;
    for (int w = 1; w < limit; w += 2) nz |= ei[w];
    g_is64 = (nz == 0) ? 1 : 0;
}

__device__ __forceinline__ int edge_at(const int* ei, int is64, long long elem) {
    return is64 ? ei[2 * elem] : ei[elem];   // low word if int64
}

// ---------------------------------------------------------------- zero
__global__ void k_zero(int n) {
    int i = blockIdx.x * blockDim.x + threadIdx.x;
    if (i < n) g_deg[i] = 0.0f;
    if (i < DD) g_pool[i] = 0.0f;
}

// ---------------------------------------------------------------- degree
__global__ void k_deg(const int* __restrict__ ei, int E, int N) {
    int e = blockIdx.x * blockDim.x + threadIdx.x;
    if (e >= E) return;
    int is64 = g_is64;
    int dst = edge_at(ei, is64, (long long)E + e);   // row 1 = aggregation targets
    if ((unsigned)dst < (unsigned)N)                 // guard: no wild atomics, ever
        atomicAdd(&g_deg[dst], 1.0f);
}

// ---------------------------------------------------------------- init: dinv + self-loop term
// s[i][:] = dinv(i)^2 * x[i][:]   (doubles as the zero-init of s)
__global__ void k_init(const float4* __restrict__ x4, int N) {
    int t = blockIdx.x * blockDim.x + threadIdx.x;   // t = i*32 + c
    if (t >= N * 32) return;
    int i = t >> 5;
    float dinv = rsqrtf(g_deg[i] + 1.0f);            // +1 = self loop
    if ((t & 31) == 0) g_dinv[i] = dinv;
    float sc = dinv * dinv;
    float4 v = x4[t];
    ((float4*)g_s)[t] = make_float4(sc * v.x, sc * v.y, sc * v.z, sc * v.w);
}

// ---------------------------------------------------------------- edge scatter (one warp per edge)
__global__ void k_scatter(const int* __restrict__ ei,
                          const float4* __restrict__ x4, int E, int N) {
    int warp = (blockIdx.x * blockDim.x + threadIdx.x) >> 5;
    int lane = threadIdx.x & 31;
    if (warp >= E) return;
    int is64 = g_is64;
    int src = edge_at(ei, is64, warp);
    int dst = edge_at(ei, is64, (long long)E + warp);
    if ((unsigned)src >= (unsigned)N || (unsigned)dst >= (unsigned)N) return;
    float nrm = g_dinv[src] * g_dinv[dst];
    float4 v = x4[(size_t)src * 32 + lane];
    float* sd = g_s + (size_t)dst * DD + lane * 4;
    atomicAdd(sd + 0, nrm * v.x);
    atomicAdd(sd + 1, nrm * v.y);
    atomicAdd(sd + 2, nrm * v.z);
    atomicAdd(sd + 3, nrm * v.w);
}

// ---------------------------------------------------------------- fused GEMM + bias + relu + residual + sum-pool
// conv = s @ W + b ; h = relu(conv) + x ; g_pool += colsum(h)
// 256 threads = 8 warps; warp -> 8 nodes; lane -> 4 consecutive cols.
// Static shared only: 32KB s-row staging + 16KB W K-tile (K looped in 4 tiles of 32).
__global__ void k_gemm(const float* __restrict__ Wg,
                       const float* __restrict__ bg,
                       const float4* __restrict__ x4,
                       int N) {
    __shared__ float Wsh[32 * 128];      // 16 KB: one K-tile of W
    __shared__ float srow[64 * 128];     // 32 KB: 8 warps * 8 nodes * 128

    int t = threadIdx.x;
    int w = t >> 5, lane = t & 31;
    int base = blockIdx.x * 64 + w * 8;
    int nn = N - base; nn = nn < 0 ? 0 : (nn > 8 ? 8 : nn);

    // stage this warp's s-rows (warp-private region -> __syncwarp suffices)
    {
        float4* sr4 = (float4*)(srow + w * 1024);
        const float4* gs4 = (const float4*)g_s;
        for (int n = 0; n < nn; n++)
            sr4[n * 32 + lane] = gs4[(size_t)(base + n) * 32 + lane];
        __syncwarp();
    }

    float acc[8][4];
    #pragma unroll
    for (int n = 0; n < 8; n++)
        acc[n][0] = acc[n][1] = acc[n][2] = acc[n][3] = 0.f;

    float4* Wsh4 = (float4*)Wsh;
    for (int kt = 0; kt < 4; kt++) {
        __syncthreads();                 // protect Wsh reuse
        const float4* Wg4 = (const float4*)(Wg + kt * 32 * 128);
        #pragma unroll
        for (int idx = t; idx < 1024; idx += 256) Wsh4[idx] = Wg4[idx];
        __syncthreads();

        const float* sw = srow + w * 1024 + kt * 32;
        #pragma unroll 8
        for (int kk = 0; kk < 32; kk++) {
            float4 wv = Wsh4[kk * 32 + lane];       // W[kt*32+kk][4l..4l+3]
            #pragma unroll
            for (int n = 0; n < 8; n++) {
                float sv = sw[n * 128 + kk];        // smem broadcast
                acc[n][0] += sv * wv.x;
                acc[n][1] += sv * wv.y;
                acc[n][2] += sv * wv.z;
                acc[n][3] += sv * wv.w;
            }
        }
    }

    // epilogue: bias + relu + residual, accumulate pool in registers
    float pool0 = 0.f, pool1 = 0.f, pool2 = 0.f, pool3 = 0.f;
    {
        float4 bgv = ((const float4*)bg)[lane];
        for (int n = 0; n < nn; n++) {
            float4 xv = x4[(size_t)(base + n) * 32 + lane];
            pool0 += fmaxf(acc[n][0] + bgv.x, 0.f) + xv.x;
            pool1 += fmaxf(acc[n][1] + bgv.y, 0.f) + xv.y;
            pool2 += fmaxf(acc[n][2] + bgv.z, 0.f) + xv.z;
            pool3 += fmaxf(acc[n][3] + bgv.w, 0.f) + xv.w;
        }
    }

    // cross-warp pool reduction via Wsh scratch (no shared atomics)
    __syncthreads();
    Wsh[w * 128 + lane * 4 + 0] = pool0;
    Wsh[w * 128 + lane * 4 + 1] = pool1;
    Wsh[w * 128 + lane * 4 + 2] = pool2;
    Wsh[w * 128 + lane * 4 + 3] = pool3;
    __syncthreads();
    if (t < DD) {
        float s = 0.f;
        #pragma unroll
        for (int w2 = 0; w2 < 8; w2++) s += Wsh[w2 * 128 + t];
        atomicAdd(&g_pool[t], s);
    }
}

// ---------------------------------------------------------------- MLP head: 128 -> 32 -> 32 -> 1 (one warp)
__global__ void k_mlp(const float* __restrict__ W1, const float* __restrict__ b1,
                      const float* __restrict__ W2, const float* __restrict__ b2,
                      const float* __restrict__ W3, const float* __restrict__ b3,
                      float* __restrict__ out) {
    int h = threadIdx.x;  // 0..31
    float a = b1[h];
    #pragma unroll 8
    for (int k = 0; k < 128; k++) a += g_pool[k] * W1[k * 32 + h];
    a = fmaxf(a, 0.f);

    float a2 = b2[h];
    #pragma unroll
    for (int m = 0; m < 32; m++)
        a2 += __shfl_sync(0xffffffffu, a, m) * W2[m * 32 + h];
    a2 = fmaxf(a2, 0.f);

    float v = a2 * W3[h];
    #pragma unroll
    for (int o = 16; o > 0; o >>= 1) v += __shfl_xor_sync(0xffffffffu, v, o);
    if (h == 0) out[0] = v + b3[0];
}

// ---------------------------------------------------------------- launcher (kernel launches ONLY)
extern "C" void kernel_launch(void* const* d_in, const int* in_sizes, int n_in,
                              void* d_out, int out_size) {
    const float* x  = (const float*)d_in[0];
    const int*   ei = (const int*)d_in[1];   // dtype resolved on-device by k_sniff
    const float* Wg = (const float*)d_in[2];
    const float* bg = (const float*)d_in[3];
    const float* W1 = (const float*)d_in[4];
    const float* b1 = (const float*)d_in[5];
    const float* W2 = (const float*)d_in[6];
    const float* b2 = (const float*)d_in[7];
    const float* W3 = (const float*)d_in[8];
    const float* b3 = (const float*)d_in[9];

    int N = in_sizes[0] / DD;
    int E = in_sizes[1] / 2;

    k_sniff<<<1, 1>>>(ei, E);
    k_zero<<<(N + 255) / 256, 256>>>(N);
    k_deg<<<(E + 255) / 256, 256>>>(ei, E, N);
    k_init<<<(N * 32 + 255) / 256, 256>>>((const float4*)x, N);
    k_scatter<<<(E + 7) / 8, 256>>>(ei, (const float4*)x, E, N);
    k_gemm<<<(N + 63) / 64, 256>>>(Wg, bg, (const float4*)x, N);
    k_mlp<<<1, 32>>>(W1, b1, W2, b2, W3, b3, (float*)d_out);
}

// round 15
// speedup vs baseline: 2.1080x; 2.1080x over previous
#include <cuda_runtime.h>

#define DD 128
#define MAXN 50176
#define MAXE 1600000

// Scratch (device globals: allocation inside kernel_launch is forbidden)
__device__ float g_dinv[MAXN];
__device__ __align__(16) float g_s[(size_t)MAXN * DD];   // ~25.7 MB, fits L2
__device__ float g_pool[DD];
__device__ int   g_is64;         // edge_index dtype flag (auto-detected on device)
__device__ int   g_cnt[MAXN];    // in-degree histogram
__device__ int   g_off[MAXN + 1];// CSR row offsets
__device__ int   g_cur[MAXN];    // fill cursors
__device__ int   g_csrc[MAXE];   // CSR: src node per bucketed edge

// ---------------------------------------------------------------- dtype sniff
// int64 little-endian with values < 2^31  =>  all odd 32-bit words are 0.
__global__ void k_sniff(const int* __restrict__ ei, int E) {
    int nz = 0;
    int limit = 2 * E < 512 ? 2 * E : 512;
    for (int w = 1; w < limit; w += 2) nz |= ei[w];
    g_is64 = (nz == 0) ? 1 : 0;
}

__device__ __forceinline__ int edge_at(const int* ei, int is64, long long elem) {
    return is64 ? ei[2 * elem] : ei[elem];   // low word if int64
}

// ---------------------------------------------------------------- zero
__global__ void k_zero(int n) {
    int i = blockIdx.x * blockDim.x + threadIdx.x;
    if (i < n) g_cnt[i] = 0;
    if (i < DD) g_pool[i] = 0.0f;
}

// ---------------------------------------------------------------- in-degree histogram (int)
__global__ void k_count(const int* __restrict__ ei, int E, int N) {
    int e = blockIdx.x * blockDim.x + threadIdx.x;
    if (e >= E) return;
    int is64 = g_is64;
    int src = edge_at(ei, is64, e);
    int dst = edge_at(ei, is64, (long long)E + e);
    if ((unsigned)src >= (unsigned)N || (unsigned)dst >= (unsigned)N) return;
    atomicAdd(&g_cnt[dst], 1);
}

// ---------------------------------------------------------------- dinv from counts
__global__ void k_dinv(int N) {
    int i = blockIdx.x * blockDim.x + threadIdx.x;
    if (i < N) g_dinv[i] = rsqrtf((float)g_cnt[i] + 1.0f);   // +1 = self loop
}

// ---------------------------------------------------------------- exclusive prefix sum (single block)
__global__ void k_scan(int N) {
    __shared__ int sh[1024];
    __shared__ int carry_s;
    int t = threadIdx.x;
    if (t == 0) carry_s = 0;
    __syncthreads();
    for (int base = 0; base < N; base += 1024) {
        int v = (base + t < N) ? g_cnt[base + t] : 0;
        sh[t] = v;
        __syncthreads();
        #pragma unroll
        for (int s = 1; s < 1024; s <<= 1) {
            int a = (t >= s) ? sh[t - s] : 0;
            __syncthreads();
            sh[t] += a;
            __syncthreads();
        }
        int excl = carry_s + sh[t] - v;          // read carry BEFORE update (sync below)
        if (base + t < N) { g_off[base + t] = excl; g_cur[base + t] = excl; }
        __syncthreads();
        if (t == 0) carry_s += sh[1023];
        __syncthreads();
    }
    if (t == 0) g_off[N] = carry_s;
}

// ---------------------------------------------------------------- bucket fill (1 int atomic + 1 store per edge)
__global__ void k_fill(const int* __restrict__ ei, int E, int N) {
    int e = blockIdx.x * blockDim.x + threadIdx.x;
    if (e >= E) return;
    int is64 = g_is64;
    int src = edge_at(ei, is64, e);
    int dst = edge_at(ei, is64, (long long)E + e);
    if ((unsigned)src >= (unsigned)N || (unsigned)dst >= (unsigned)N) return;
    int pos = atomicAdd(&g_cur[dst], 1);
    if (pos < MAXE) g_csrc[pos] = src;
}

// ---------------------------------------------------------------- CSR gather: one warp per dst node
// s[i] = dinv_i^2 * x[i]  +  sum_{src in bucket(i)} dinv_src*dinv_i * x[src]
__global__ void k_gather(const float4* __restrict__ x4, int N) {
    int warp = (blockIdx.x * blockDim.x + threadIdx.x) >> 5;
    int lane = threadIdx.x & 31;
    if (warp >= N) return;
    int i = warp;
    float dinv_i = g_dinv[i];

    float4 acc = x4[(size_t)i * 32 + lane];      // self-loop term
    float sc = dinv_i * dinv_i;
    acc.x *= sc; acc.y *= sc; acc.z *= sc; acc.w *= sc;

    int off = g_off[i], end = g_off[i + 1];
    for (int base = off; base < end; base += 32) {
        int myidx = (base + lane < end) ? g_csrc[base + lane] : 0;
        int cnt = end - base; if (cnt > 32) cnt = 32;
        for (int k = 0; k < cnt; k++) {
            int src = __shfl_sync(0xffffffffu, myidx, k);
            float nrm = g_dinv[src] * dinv_i;    // same-addr load -> broadcast
            float4 v = x4[(size_t)src * 32 + lane];
            acc.x += nrm * v.x; acc.y += nrm * v.y;
            acc.z += nrm * v.z; acc.w += nrm * v.w;
        }
    }
    ((float4*)g_s)[(size_t)i * 32 + lane] = acc; // single plain store per row
}

// ---------------------------------------------------------------- fused GEMM + bias + relu + residual + sum-pool
__global__ void k_gemm(const float* __restrict__ Wg,
                       const float* __restrict__ bg,
                       const float4* __restrict__ x4,
                       int N) {
    __shared__ float Wsh[32 * 128];      // 16 KB: one K-tile of W
    __shared__ float srow[64 * 128];     // 32 KB: 8 warps * 8 nodes * 128

    int t = threadIdx.x;
    int w = t >> 5, lane = t & 31;
    int base = blockIdx.x * 64 + w * 8;
    int nn = N - base; nn = nn < 0 ? 0 : (nn > 8 ? 8 : nn);

    {
        float4* sr4 = (float4*)(srow + w * 1024);
        const float4* gs4 = (const float4*)g_s;
        for (int n = 0; n < nn; n++)
            sr4[n * 32 + lane] = gs4[(size_t)(base + n) * 32 + lane];
        __syncwarp();
    }

    float acc[8][4];
    #pragma unroll
    for (int n = 0; n < 8; n++)
        acc[n][0] = acc[n][1] = acc[n][2] = acc[n][3] = 0.f;

    float4* Wsh4 = (float4*)Wsh;
    for (int kt = 0; kt < 4; kt++) {
        __syncthreads();
        const float4* Wg4 = (const float4*)(Wg + kt * 32 * 128);
        #pragma unroll
        for (int idx = t; idx < 1024; idx += 256) Wsh4[idx] = Wg4[idx];
        __syncthreads();

        const float* sw = srow + w * 1024 + kt * 32;
        #pragma unroll 8
        for (int kk = 0; kk < 32; kk++) {
            float4 wv = Wsh4[kk * 32 + lane];
            #pragma unroll
            for (int n = 0; n < 8; n++) {
                float sv = sw[n * 128 + kk];
                acc[n][0] += sv * wv.x;
                acc[n][1] += sv * wv.y;
                acc[n][2] += sv * wv.z;
                acc[n][3] += sv * wv.w;
            }
        }
    }

    float pool0 = 0.f, pool1 = 0.f, pool2 = 0.f, pool3 = 0.f;
    {
        float4 bgv = ((const float4*)bg)[lane];
        for (int n = 0; n < nn; n++) {
            float4 xv = x4[(size_t)(base + n) * 32 + lane];
            pool0 += fmaxf(acc[n][0] + bgv.x, 0.f) + xv.x;
            pool1 += fmaxf(acc[n][1] + bgv.y, 0.f) + xv.y;
            pool2 += fmaxf(acc[n][2] + bgv.z, 0.f) + xv.z;
            pool3 += fmaxf(acc[n][3] + bgv.w, 0.f) + xv.w;
        }
    }

    __syncthreads();
    Wsh[w * 128 + lane * 4 + 0] = pool0;
    Wsh[w * 128 + lane * 4 + 1] = pool1;
    Wsh[w * 128 + lane * 4 + 2] = pool2;
    Wsh[w * 128 + lane * 4 + 3] = pool3;
    __syncthreads();
    if (t < DD) {
        float s = 0.f;
        #pragma unroll
        for (int w2 = 0; w2 < 8; w2++) s += Wsh[w2 * 128 + t];
        atomicAdd(&g_pool[t], s);
    }
}

// ---------------------------------------------------------------- MLP head: 128 -> 32 -> 32 -> 1 (one warp)
__global__ void k_mlp(const float* __restrict__ W1, const float* __restrict__ b1,
                      const float* __restrict__ W2, const float* __restrict__ b2,
                      const float* __restrict__ W3, const float* __restrict__ b3,
                      float* __restrict__ out) {
    int h = threadIdx.x;  // 0..31
    float a = b1[h];
    #pragma unroll 8
    for (int k = 0; k < 128; k++) a += g_pool[k] * W1[k * 32 + h];
    a = fmaxf(a, 0.f);

    float a2 = b2[h];
    #pragma unroll
    for (int m = 0; m < 32; m++)
        a2 += __shfl_sync(0xffffffffu, a, m) * W2[m * 32 + h];
    a2 = fmaxf(a2, 0.f);

    float v = a2 * W3[h];
    #pragma unroll
    for (int o = 16; o > 0; o >>= 1) v += __shfl_xor_sync(0xffffffffu, v, o);
    if (h == 0) out[0] = v + b3[0];
}

// ---------------------------------------------------------------- launcher (kernel launches ONLY)
extern "C" void kernel_launch(void* const* d_in, const int* in_sizes, int n_in,
                              void* d_out, int out_size) {
    const float* x  = (const float*)d_in[0];
    const int*   ei = (const int*)d_in[1];   // dtype resolved on-device by k_sniff
    const float* Wg = (const float*)d_in[2];
    const float* bg = (const float*)d_in[3];
    const float* W1 = (const float*)d_in[4];
    const float* b1 = (const float*)d_in[5];
    const float* W2 = (const float*)d_in[6];
    const float* b2 = (const float*)d_in[7];
    const float* W3 = (const float*)d_in[8];
    const float* b3 = (const float*)d_in[9];

    int N = in_sizes[0] / DD;
    int E = in_sizes[1] / 2;

    k_sniff<<<1, 1>>>(ei, E);
    k_zero<<<(N + 255) / 256, 256>>>(N);
    k_count<<<(E + 255) / 256, 256>>>(ei, E, N);
    k_dinv<<<(N + 255) / 256, 256>>>(N);
    k_scan<<<1, 1024>>>(N);
    k_fill<<<(E + 255) / 256, 256>>>(ei, E, N);
    k_gather<<<(N * 32 + 255) / 256, 256>>>((const float4*)x, N);
    k_gemm<<<(N + 63) / 64, 256>>>(Wg, bg, (const float4*)x, N);
    k_mlp<<<1, 32>>>(W1, b1, W2, b2, W3, b3, (float*)d_out);
}